// round 7
// baseline (speedup 1.0000x reference)
#include <cuda_runtime.h>
#include <cuda_bf16.h>
#include <cstdint>

// ---------------------------------------------------------------------------
// Problem constants
// ---------------------------------------------------------------------------
#define NROWS 2048
#define NFEAT 128
#define TILE  128
#define GRID  256                 // 16x16 tiles; all co-resident at 2/SM
#define NTHREADS 512              // 16 warps per CTA

// ---------------------------------------------------------------------------
// Device scratch (zero-initialized; no allocation allowed)
// ---------------------------------------------------------------------------
__device__ __nv_bfloat16 g_Xb[NROWS * NFEAT];   // bf16-quantized X
__device__ float g_norm[NROWS];                 // row norms of quantized X
__device__ float g_s_part[GRID][NFEAT];         // per-CTA feature-sum partials
__device__ float g_sumn_part[GRID];             // per-CTA sum-of-norms partials
__device__ float g_s2[8][NFEAT];                // level-2 feature-sum partials
__device__ float g_sn2[8];                      // level-2 sum-of-norms partials
__device__ float g_c;                           // inv2s * log2(e)
__device__ int   g_ctr;                         // phase-1 arrive counter
__device__ int   g_ctr3;                        // level-2 arrive counter
__device__ int   g_ctr2;                        // exit counter (for reset)
__device__ int   g_flag1;                       // phase-1 data visible
__device__ int   g_flag2;                       // sigma ready

// ---------------------------------------------------------------------------
// Helpers
// ---------------------------------------------------------------------------
__device__ __forceinline__ uint32_t smem_to_u32(const void* p) {
    uint32_t a;
    asm("{ .reg .u64 t; cvta.to.shared.u64 t, %1; cvt.u32.u64 %0, t; }" : "=r"(a) : "l"(p));
    return a;
}

__device__ __forceinline__ void ldmatrix_x4(uint32_t& r0, uint32_t& r1,
                                            uint32_t& r2, uint32_t& r3, uint32_t addr) {
    asm volatile("ldmatrix.sync.aligned.m8n8.x4.shared.b16 {%0,%1,%2,%3}, [%4];"
                 : "=r"(r0), "=r"(r1), "=r"(r2), "=r"(r3) : "r"(addr));
}

__device__ __forceinline__ void mma_16816(float* d, const uint32_t* a, const uint32_t* b) {
    asm volatile(
        "mma.sync.aligned.m16n8k16.row.col.f32.bf16.bf16.f32 "
        "{%0,%1,%2,%3}, {%4,%5,%6,%7}, {%8,%9}, {%0,%1,%2,%3};"
        : "+f"(d[0]), "+f"(d[1]), "+f"(d[2]), "+f"(d[3])
        : "r"(a[0]), "r"(a[1]), "r"(a[2]), "r"(a[3]), "r"(b[0]), "r"(b[1]));
}

__device__ __forceinline__ float ex2f(float x) {
    float r;
    asm("ex2.approx.ftz.f32 %0, %1;" : "=f"(r) : "f"(x));
    return r;
}

__device__ __forceinline__ void spin_until(volatile int* fp) {
    while (*fp == 0) { __nanosleep(32); }
}

// ---------------------------------------------------------------------------
// Smem layout (dynamic, 66560 B): ci/cj const tiles + A/B bf16 tiles.
// OFF_A region reused: phase-1 partials, level-2 scratch, tiles.
// ---------------------------------------------------------------------------
#define OFF_CI  0
#define OFF_CJ  512
#define OFF_A   1024
#define OFF_B   (1024 + 32768)
#define SMEM_TOTAL (OFF_B + 32768)

// ---------------------------------------------------------------------------
// ONE fused kernel, 512 threads, 2 CTAs/SM (32 warps/SM on doubled SMs).
// flag1 gates tile loads; sigma (flag2, computed by 8 CTAs two-level,
// concurrent with GEMM) gates only the epilogue.
// ---------------------------------------------------------------------------
__global__ void __launch_bounds__(NTHREADS, 2) gauss_fused_kernel(
        const float* __restrict__ X, float* __restrict__ out) {
    extern __shared__ char smem[];
    uint32_t sb = smem_to_u32(smem);
    int b   = blockIdx.x;
    int tid = threadIdx.x;
    int wid = tid >> 5;
    int lid = tid & 31;

    __shared__ float sn[8];
    __shared__ float red[5];
    __shared__ int   s_last3;

    // =============== Phase 1: quantize 8 rows, partials (warps 0-7) ========
    {
        float* ss = reinterpret_cast<float*>(smem + OFF_A);   // [8][128]
        if (wid < 8) {
            int row = b * 8 + wid;                            // warp owns one row
            float4 v = reinterpret_cast<const float4*>(X + (size_t)row * NFEAT)[lid];
            __nv_bfloat16 b0 = __float2bfloat16(v.x);
            __nv_bfloat16 b1 = __float2bfloat16(v.y);
            __nv_bfloat16 b2 = __float2bfloat16(v.z);
            __nv_bfloat16 b3 = __float2bfloat16(v.w);
            __nv_bfloat162* dst =
                reinterpret_cast<__nv_bfloat162*>(g_Xb + (size_t)row * NFEAT) + lid * 2;
            dst[0] = __nv_bfloat162(b0, b1);
            dst[1] = __nv_bfloat162(b2, b3);
            // quantized values downstream (diag exactly 0 -> out = 1)
            float fx = __bfloat162float(b0), fy = __bfloat162float(b1);
            float fz = __bfloat162float(b2), fw = __bfloat162float(b3);
            float sq = fx * fx + fy * fy + fz * fz + fw * fw;
            #pragma unroll
            for (int o = 16; o > 0; o >>= 1) sq += __shfl_xor_sync(0xFFFFFFFFu, sq, o);
            if (lid == 0) { g_norm[row] = sq; sn[wid] = sq; }
            ss[wid * NFEAT + lid * 4 + 0] = fx;
            ss[wid * NFEAT + lid * 4 + 1] = fy;
            ss[wid * NFEAT + lid * 4 + 2] = fz;
            ss[wid * NFEAT + lid * 4 + 3] = fw;
        }
        __syncthreads();
        if (tid < NFEAT) {
            float t = 0.f;
            #pragma unroll
            for (int w = 0; w < 8; w++) t += ss[w * NFEAT + tid];
            g_s_part[b][tid] = t;
        }
        if (tid == 0) {
            float t = 0.f;
            #pragma unroll
            for (int w = 0; w < 8; w++) t += sn[w];
            g_sumn_part[b] = t;
        }
    }

    // =============== Barrier: release flag1 immediately ===============
    __threadfence();
    __syncthreads();
    if (tid == 0) {
        if (atomicAdd(&g_ctr, 1) == GRID - 1)
            *((volatile int*)&g_flag1) = 1;       // data visible -> everyone go
        else
            spin_until(&g_flag1);
    }
    __syncthreads();

    // =============== Level-2 sigma reduction on CTAs 0..7 (concurrent) =====
    if (b < 8) {
        float* ss2 = reinterpret_cast<float*>(smem + OFF_A);  // [4][128]
        {
            int f = tid & 127;
            int g = tid >> 7;                     // 0..3, 8 partials each
            float sf = 0.f;
            #pragma unroll
            for (int p = b * 32 + g * 8; p < b * 32 + g * 8 + 8; p++)
                sf += __ldcg(&g_s_part[p][f]);
            ss2[g * NFEAT + f] = sf;
        }
        if (tid < 32) {
            float sna = __ldcg(&g_sumn_part[b * 32 + tid]);
            #pragma unroll
            for (int o = 16; o > 0; o >>= 1) sna += __shfl_xor_sync(0xFFFFFFFFu, sna, o);
            if (tid == 0) g_sn2[b] = sna;
        }
        __syncthreads();
        if (tid < NFEAT) {
            g_s2[b][tid] = ss2[tid] + ss2[NFEAT + tid] +
                           ss2[2 * NFEAT + tid] + ss2[3 * NFEAT + tid];
        }
        __threadfence();
        __syncthreads();
        if (tid == 0) s_last3 = (atomicAdd(&g_ctr3, 1) == 7) ? 1 : 0;
        __syncthreads();
        if (s_last3) {
            if (tid < NFEAT) {
                float s = 0.f;
                #pragma unroll
                for (int q = 0; q < 8; q++) s += __ldcg(&g_s2[q][tid]);
                float v = s * s;
                #pragma unroll
                for (int o = 16; o > 0; o >>= 1) v += __shfl_xor_sync(0xFFFFFFFFu, v, o);
                if (lid == 0) red[wid] = v;
            }
            if (tid >= 480) {   // one spare warp sums sn2
                float sna = (lid < 8) ? __ldcg(&g_sn2[lid]) : 0.f;
                #pragma unroll
                for (int o = 4; o > 0; o >>= 1) sna += __shfl_xor_sync(0xFFFFFFFFu, sna, o);
                if (lid == 0) red[4] = sna;
            }
            __syncthreads();
            if (tid == 0) {
                float S2   = red[0] + red[1] + red[2] + red[3];
                float sumn = red[4];
                float Nf = (float)NROWS;
                float inv2s = (Nf * Nf) / (4.f * Nf * sumn - 4.f * S2);
                g_c = inv2s * 1.4426950408889634f;   // fold log2(e) for ex2
                __threadfence();
                *((volatile int*)&g_flag2) = 1;
            }
        }
        __syncthreads();   // OFF_A about to be reused for tiles
    }

    // =============== Phase 3: GEMM tile (sigma NOT needed yet) ===========
    int bj = b & 15;
    int bi = b >> 4;

    // prefetch raw norms (visible since flag1): tid<128 -> ni, 128..255 -> nj
    float n_pref = 0.f;
    if (tid < TILE)           n_pref = __ldcg(&g_norm[bi * TILE + tid]);
    else if (tid < 2 * TILE)  n_pref = __ldcg(&g_norm[bj * TILE + (tid - TILE)]);

    // load A/B tiles into swizzled smem (L2-coherent reads of phase-1 data)
    const uint4* A4 = reinterpret_cast<const uint4*>(g_Xb + (size_t)bi * TILE * NFEAT);
    const uint4* B4 = reinterpret_cast<const uint4*>(g_Xb + (size_t)bj * TILE * NFEAT);
    #pragma unroll
    for (int idx = tid; idx < 2048; idx += NTHREADS) {
        int row = idx >> 4;
        int ch  = idx & 15;
        uint32_t off = (uint32_t)row * 256u + (uint32_t)(ch ^ (row & 7)) * 16u;
        *reinterpret_cast<uint4*>(smem + OFF_A + off) = __ldcg(&A4[idx]);
        *reinterpret_cast<uint4*>(smem + OFF_B + off) = __ldcg(&B4[idx]);
    }
    __syncthreads();

    // per-warp MMA: 16 warps as 4x4 grid of 32x32 subtiles
    int wm  = (wid & 3) * 32;
    int wn2 = (wid >> 2) * 32;

    float d[2][4][4];
    #pragma unroll
    for (int mt = 0; mt < 2; mt++)
        #pragma unroll
        for (int nt = 0; nt < 4; nt++)
            #pragma unroll
            for (int e = 0; e < 4; e++) d[mt][nt][e] = 0.f;

    uint32_t a_row  = (uint32_t)(wm + (lid & 15));
    uint32_t a_cbit = (uint32_t)(lid >> 4);
    uint32_t a_rl   = a_row & 7;
    uint32_t a_base0 = sb + OFF_A + a_row * 256u;
    uint32_t a_base1 = a_base0 + 16u * 256u;

    uint32_t b_row  = (uint32_t)(wn2 + (lid & 7) + ((lid & 16) >> 1));
    uint32_t b_cbit = (uint32_t)((lid >> 3) & 1);
    uint32_t b_rl   = b_row & 7;
    uint32_t b_base0 = sb + OFF_B + b_row * 256u;
    uint32_t b_base1 = b_base0 + 16u * 256u;

    #pragma unroll
    for (int kc = 0; kc < 8; kc++) {
        uint32_t af[2][4];
        uint32_t bf[4][2];
        {
            uint32_t sca = ((uint32_t)(2 * kc) + a_cbit) ^ a_rl;
            ldmatrix_x4(af[0][0], af[0][1], af[0][2], af[0][3], a_base0 + (sca << 4));
            ldmatrix_x4(af[1][0], af[1][1], af[1][2], af[1][3], a_base1 + (sca << 4));
            uint32_t scb = ((uint32_t)(2 * kc) + b_cbit) ^ b_rl;
            ldmatrix_x4(bf[0][0], bf[0][1], bf[1][0], bf[1][1], b_base0 + (scb << 4));
            ldmatrix_x4(bf[2][0], bf[2][1], bf[3][0], bf[3][1], b_base1 + (scb << 4));
        }
        #pragma unroll
        for (int mt = 0; mt < 2; mt++)
            #pragma unroll
            for (int nt = 0; nt < 4; nt++)
                mma_16816(d[mt][nt], af[mt], bf[nt]);
    }

    // =============== Wait for sigma (already done for most CTAs) =========
    if (tid == 0) spin_until(&g_flag2);
    __syncthreads();
    float c = __ldcg(&g_c);

    // write const tiles: ci = -ni*c, cj = -nj*c
    if (tid < TILE)
        reinterpret_cast<float*>(smem + OFF_CI)[tid] = -n_pref * c;
    else if (tid < 2 * TILE)
        reinterpret_cast<float*>(smem + OFF_CJ)[tid - TILE] = -n_pref * c;
    __syncthreads();

    // epilogue: out = ex2(dot * 2c + ci + cj)
    float sc2 = 2.f * c;
    const float* cis = reinterpret_cast<const float*>(smem + OFF_CI);
    const float* cjs = reinterpret_cast<const float*>(smem + OFF_CJ);
    int quad = lid >> 2;
    int qt   = lid & 3;

    #pragma unroll
    for (int mt = 0; mt < 2; mt++) {
        #pragma unroll
        for (int half = 0; half < 2; half++) {
            int r  = wm + mt * 16 + quad + half * 8;
            float ci = cis[r];
            float* orow = out + (size_t)(bi * TILE + r) * NROWS + (size_t)bj * TILE + wn2;
            #pragma unroll
            for (int nt = 0; nt < 4; nt++) {
                int col = nt * 8 + qt * 2;
                float e0 = fmaf(d[mt][nt][half * 2 + 0], sc2, ci + cjs[wn2 + col]);
                float e1 = fmaf(d[mt][nt][half * 2 + 1], sc2, ci + cjs[wn2 + col + 1]);
                *reinterpret_cast<float2*>(orow + col) = make_float2(ex2f(e0), ex2f(e1));
            }
        }
    }

    // =============== reset counters for next graph replay ===============
    __syncthreads();
    if (tid == 0) {
        int a2 = atomicAdd(&g_ctr2, 1);
        if (a2 == GRID - 1) {          // everyone has passed both flags
            g_ctr   = 0;
            g_ctr3  = 0;
            g_ctr2  = 0;
            g_flag1 = 0;
            g_flag2 = 0;
        }
    }
}

// ---------------------------------------------------------------------------
// Launch
// ---------------------------------------------------------------------------
extern "C" void kernel_launch(void* const* d_in, const int* in_sizes, int n_in,
                              void* d_out, int out_size) {
    const float* X = (const float*)d_in[0];
    float* out = (float*)d_out;
    (void)in_sizes; (void)n_in; (void)out_size;

    cudaFuncSetAttribute(gauss_fused_kernel,
                         cudaFuncAttributeMaxDynamicSharedMemorySize, SMEM_TOTAL);

    gauss_fused_kernel<<<GRID, NTHREADS, SMEM_TOTAL>>>(X, out);
}